// round 1
// baseline (speedup 1.0000x reference)
#include <cuda_runtime.h>

// Problem constants
#define SN 4096      // sequence length
#define HN 1024      // hidden
#define BN 4         // batch
#define RN 16        // rules
#define NP 40        // padded N for stage-1 GEMM (16 wc + 16 we + 1 besum + 7 pad)

// ---------------- scratch (device globals; no allocation) ----------------
__device__ float  g_W[NP * HN];           // rows 0-15 wc, 16-31 we, 32 besum, 33-39 zero
__device__ float2 g_P[BN * SN * RN];      // scaled cause scores, duplicated {p,p}
__device__ float  g_Ut[BN * RN * SN];     // effect dot, r-major (t contiguous)
__device__ float  g_V[BN * SN];           // bias-term dot

// packed f32x2 FMA (SASS FFMA2) — 2x fp32 FMA throughput vs 3-reg FFMA
__device__ __forceinline__ float2 ffma2(float2 a, float2 b, float2 c) {
    float2 d;
    asm("fma.rn.f32x2 %0, %1, %2, %3;"
        : "=l"(*reinterpret_cast<unsigned long long*>(&d))
        : "l"(*reinterpret_cast<unsigned long long*>(&a)),
          "l"(*reinterpret_cast<unsigned long long*>(&b)),
          "l"(*reinterpret_cast<unsigned long long*>(&c)));
    return d;
}

// ---------------- kernel 0: build packed weight matrix ----------------
__global__ void k0_build(const float* __restrict__ wc,
                         const float* __restrict__ we,
                         const float* __restrict__ be) {
    int n = blockIdx.x;                 // 0..32
    for (int h = threadIdx.x; h < HN; h += blockDim.x) {
        float v;
        if (n < 16)      v = wc[n * HN + h];
        else if (n < 32) v = we[(n - 16) * HN + h];
        else {
            v = 0.f;
            #pragma unroll
            for (int r = 0; r < RN; r++) v += be[r * HN + h];
        }
        g_W[n * HN + h] = v;
    }
}

// ---------------- kernel 1: [16384 x 1024] @ [1024 x 40] with f32x2 along K ----
#define K1_BM 128
#define K1_KC 32
#define K1_PITCH 36    // float pitch: 16B-aligned rows, 2-way-max LDS conflicts

__global__ __launch_bounds__(256)
void k1_proj(const float* __restrict__ hs,
             const float* __restrict__ bc,
             const float* __restrict__ strength) {
    __shared__ __align__(16) float As[K1_BM * K1_PITCH];  // 18.4 KB
    __shared__ __align__(16) float Ws[NP * K1_PITCH];     // 5.8 KB

    const int tid = threadIdx.x;
    const int x = tid & 31;       // row lane
    const int y = tid >> 5;       // n-group (0..7), 5 outputs each
    const int rowBase = blockIdx.x * K1_BM;

    float2 acc[4][5];
    #pragma unroll
    for (int m = 0; m < 4; m++)
        #pragma unroll
        for (int nn = 0; nn < 5; nn++) acc[m][nn] = make_float2(0.f, 0.f);

    for (int k0 = 0; k0 < HN; k0 += K1_KC) {
        __syncthreads();
        // stage A tile: 128 rows x 32 k  (float4, coalesced)
        #pragma unroll
        for (int i = 0; i < 4; i++) {
            int idx = tid + 256 * i;            // < 1024 float4s
            int row = idx >> 3, k4 = idx & 7;
            float4 f = *reinterpret_cast<const float4*>(
                &hs[(rowBase + row) * HN + k0 + k4 * 4]);
            *reinterpret_cast<float4*>(&As[row * K1_PITCH + k4 * 4]) = f;
        }
        // stage W tile: 40 x 32
        #pragma unroll
        for (int i = 0; i < 5; i++) {
            int idx = tid + 256 * i;            // == 1280 total
            int n = idx >> 5, kk = idx & 31;
            Ws[n * K1_PITCH + kk] = g_W[n * HN + k0 + kk];
        }
        __syncthreads();

        #pragma unroll
        for (int kp = 0; kp < K1_KC / 2; kp++) {
            float2 a2[4], b2[5];
            #pragma unroll
            for (int m = 0; m < 4; m++)
                a2[m] = *reinterpret_cast<const float2*>(
                    &As[(x + 32 * m) * K1_PITCH + 2 * kp]);
            #pragma unroll
            for (int nn = 0; nn < 5; nn++)
                b2[nn] = *reinterpret_cast<const float2*>(
                    &Ws[(y * 5 + nn) * K1_PITCH + 2 * kp]);
            #pragma unroll
            for (int m = 0; m < 4; m++)
                #pragma unroll
                for (int nn = 0; nn < 5; nn++)
                    acc[m][nn] = ffma2(a2[m], b2[nn], acc[m][nn]);
        }
    }

    // epilogue
    #pragma unroll
    for (int m = 0; m < 4; m++) {
        int row = rowBase + x + 32 * m;
        int b = row >> 12;            // /4096
        int s = row & (SN - 1);
        #pragma unroll
        for (int nn = 0; nn < 5; nn++) {
            int n = y * 5 + nn;
            float val = acc[m][nn].x + acc[m][nn].y;
            if (n < 16) {
                float p = (val + bc[n]) * strength[n];
                g_P[(b * SN + s) * RN + n] = make_float2(p, p);
            } else if (n < 32) {
                g_Ut[(b * RN + (n - 16)) * SN + s] = val;   // coalesced along s
            } else if (n == 32) {
                g_V[b * SN + s] = val;
            }
        }
    }
}

// ---------------- kernel 2: bias[b,s,t] = sum_r P*U + V ----------------
// Block: 256 thr = 64 t-lanes (4 t each) x 4 s-groups (4 s each) -> 16 s x 256 t/iter
__global__ __launch_bounds__(256, 1)
void k2_outer(float* __restrict__ out) {
    __shared__ __align__(16) float Us[RN * 256];   // 16 KB
    __shared__ __align__(16) float Vs[256];        // 1 KB

    const int tid = threadIdx.x;
    const int x = tid & 63;        // t quad lane
    const int y = tid >> 6;        // s group 0..3
    const int b = blockIdx.z;
    const int sBase = blockIdx.y * 16 + y * 4;
    const int tQ = blockIdx.x * 1024;

    // P for my 4 s-rows, all 16 r, pre-duplicated pairs -> 128 regs
    float2 pp[4][RN];
    #pragma unroll
    for (int m = 0; m < 4; m++) {
        const float2* src = &g_P[(b * SN + sBase + m) * RN];
        #pragma unroll
        for (int r = 0; r < RN; r++) pp[m][r] = src[r];   // broadcast LDG.64
    }

    for (int it = 0; it < 4; it++) {
        int tBase = tQ + it * 256;
        // stage U chunk [16 r x 256 t] + V chunk
        #pragma unroll
        for (int i = 0; i < 4; i++) {
            int idx = tid + 256 * i;           // < 1024 float4s
            int r = idx >> 6, t4 = idx & 63;
            *reinterpret_cast<float4*>(&Us[r * 256 + t4 * 4]) =
                *reinterpret_cast<const float4*>(
                    &g_Ut[(b * RN + r) * SN + tBase + t4 * 4]);
        }
        if (tid < 64)
            *reinterpret_cast<float4*>(&Vs[tid * 4]) =
                *reinterpret_cast<const float4*>(&g_V[b * SN + tBase + tid * 4]);
        __syncthreads();

        float4 v4 = *reinterpret_cast<const float4*>(&Vs[4 * x]);
        float2 accA[4], accB[4];
        #pragma unroll
        for (int m = 0; m < 4; m++) {
            accA[m] = make_float2(v4.x, v4.y);
            accB[m] = make_float2(v4.z, v4.w);
        }
        #pragma unroll
        for (int r = 0; r < RN; r++) {
            float4 u4 = *reinterpret_cast<const float4*>(&Us[r * 256 + 4 * x]);
            float2 ua = make_float2(u4.x, u4.y);
            float2 ub = make_float2(u4.z, u4.w);
            #pragma unroll
            for (int m = 0; m < 4; m++) {
                accA[m] = ffma2(pp[m][r], ua, accA[m]);
                accB[m] = ffma2(pp[m][r], ub, accB[m]);
            }
        }
        #pragma unroll
        for (int m = 0; m < 4; m++) {
            float* o = &out[(size_t)(b * SN + sBase + m) * SN + tBase];
            *reinterpret_cast<float4*>(&o[4 * x]) =
                make_float4(accA[m].x, accA[m].y, accB[m].x, accB[m].y);
        }
        __syncthreads();
    }
}

// ---------------- launch ----------------
extern "C" void kernel_launch(void* const* d_in, const int* in_sizes, int n_in,
                              void* d_out, int out_size) {
    const float* hs       = (const float*)d_in[0];
    const float* wc       = (const float*)d_in[1];
    const float* bc       = (const float*)d_in[2];
    const float* we       = (const float*)d_in[3];
    const float* be       = (const float*)d_in[4];
    const float* strength = (const float*)d_in[5];
    float* out = (float*)d_out;

    k0_build<<<33, 256>>>(wc, we, be);
    k1_proj<<<(BN * SN) / K1_BM, 256>>>(hs, bc, strength);
    k2_outer<<<dim3(4, SN / 16, BN), 256>>>(out);
}

// round 2
// speedup vs baseline: 1.6264x; 1.6264x over previous
#include <cuda_runtime.h>

// Problem constants
#define SN 4096      // sequence length
#define HN 1024      // hidden
#define BN 4         // batch
#define RN 16        // rules

// ---------------- scratch (device globals; no allocation) ----------------
__device__ float g_Pf[BN * RN * SN];      // scaled cause scores, [b][r][s]
__device__ float g_Ut[BN * RN * SN];      // effect dot, [b][r][t]
__device__ float g_V[BN * SN];            // bias-term dot, [b][t]

// packed f32x2 FMA (SASS FFMA2) — 2x fp32 FMA throughput vs 3-reg FFMA
__device__ __forceinline__ float2 ffma2(float2 a, float2 b, float2 c) {
    float2 d;
    asm("fma.rn.f32x2 %0, %1, %2, %3;"
        : "=l"(*reinterpret_cast<unsigned long long*>(&d))
        : "l"(*reinterpret_cast<unsigned long long*>(&a)),
          "l"(*reinterpret_cast<unsigned long long*>(&b)),
          "l"(*reinterpret_cast<unsigned long long*>(&c)));
    return d;
}

__device__ __forceinline__ void cp16(void* smem_dst, const void* gmem_src) {
    unsigned sdst = (unsigned)__cvta_generic_to_shared(smem_dst);
    asm volatile("cp.async.cg.shared.global [%0], [%1], 16;"
                 :: "r"(sdst), "l"(gmem_src) : "memory");
}
__device__ __forceinline__ void cp_commit() {
    asm volatile("cp.async.commit_group;" ::: "memory");
}
__device__ __forceinline__ void cp_wait0() {
    asm volatile("cp.async.wait_group 0;" ::: "memory");
}

// =======================================================================
// kernel 1: [16384 x 1024] @ [1024 x 33] projection (wc | we | sum_be)
//   P[b,r,s] = (hs.wc_r + bc_r)*strength_r ; Ut[b,r,t] = hs.we_r ; V = hs.besum
// =======================================================================
#define K1_BM 64
#define K1_KC 32
#define K1_PITCH 36

__global__ __launch_bounds__(256, 2)
void k1_proj(const float* __restrict__ hs,
             const float* __restrict__ wc,
             const float* __restrict__ bc,
             const float* __restrict__ we,
             const float* __restrict__ be,
             const float* __restrict__ strength) {
    __shared__ float besum_s[HN];
    __shared__ __align__(16) float As[2][K1_BM * K1_PITCH];
    __shared__ __align__(16) float Ws[2][40 * K1_PITCH];

    const int tid = threadIdx.x;
    const int x = tid & 31;          // row lane
    const int y = tid >> 5;          // n-group (0..7), 5 outputs each
    const int rowBase = blockIdx.x * K1_BM;

    // zero Ws (rows 33-39 stay zero forever)
    for (int i = tid; i < 2 * 40 * K1_PITCH; i += 256)
        (&Ws[0][0])[i] = 0.f;

    // per-CTA redundant besum (fused k0): 4 cols per thread, coalesced
    #pragma unroll
    for (int j = 0; j < 4; j++) {
        int col = tid + 256 * j;
        float s = 0.f;
        #pragma unroll
        for (int r = 0; r < RN; r++) s += be[r * HN + col];
        besum_s[col] = s;
    }
    __syncthreads();

    // staging lambda-ish (macro-expanded by hand)
    auto stage = [&](int c, int buf) {
        // A tile: 64 rows x 32 k = 512 float4, 2 per thread
        #pragma unroll
        for (int i = 0; i < 2; i++) {
            int idx = tid + 256 * i;
            int row = idx >> 3, k4 = idx & 7;
            cp16(&As[buf][row * K1_PITCH + k4 * 4],
                 &hs[(size_t)(rowBase + row) * HN + c * K1_KC + k4 * 4]);
        }
        // W rows 0..31: 256 float4, 1 per thread
        {
            int n = tid >> 3, k4 = tid & 7;
            const float* src = (n < 16)
                ? &wc[n * HN + c * K1_KC + k4 * 4]
                : &we[(n - 16) * HN + c * K1_KC + k4 * 4];
            cp16(&Ws[buf][n * K1_PITCH + k4 * 4], src);
        }
        cp_commit();
        // W row 32 = besum slice (plain smem copy)
        if (tid < 32)
            Ws[buf][32 * K1_PITCH + tid] = besum_s[c * K1_KC + tid];
    };

    float2 acc[2][5];
    #pragma unroll
    for (int m = 0; m < 2; m++)
        #pragma unroll
        for (int nn = 0; nn < 5; nn++) acc[m][nn] = make_float2(0.f, 0.f);

    stage(0, 0);

    for (int c = 0; c < HN / K1_KC; c++) {
        cp_wait0();
        __syncthreads();
        if (c + 1 < HN / K1_KC) stage(c + 1, (c + 1) & 1);
        const int buf = c & 1;

        #pragma unroll
        for (int kp = 0; kp < K1_KC / 2; kp++) {
            float2 a2[2], b2[5];
            #pragma unroll
            for (int m = 0; m < 2; m++)
                a2[m] = *reinterpret_cast<const float2*>(
                    &As[buf][(x + 32 * m) * K1_PITCH + 2 * kp]);
            #pragma unroll
            for (int nn = 0; nn < 5; nn++)
                b2[nn] = *reinterpret_cast<const float2*>(
                    &Ws[buf][(y * 5 + nn) * K1_PITCH + 2 * kp]);
            #pragma unroll
            for (int m = 0; m < 2; m++)
                #pragma unroll
                for (int nn = 0; nn < 5; nn++)
                    acc[m][nn] = ffma2(a2[m], b2[nn], acc[m][nn]);
        }
        __syncthreads();
    }

    // epilogue
    #pragma unroll
    for (int m = 0; m < 2; m++) {
        int row = rowBase + x + 32 * m;
        int b = row >> 12;               // /4096
        int s = row & (SN - 1);
        #pragma unroll
        for (int nn = 0; nn < 5; nn++) {
            int n = y * 5 + nn;
            float val = acc[m][nn].x + acc[m][nn].y;
            if (n < 16) {
                g_Pf[(b * RN + n) * SN + s] = (val + bc[n]) * strength[n];
            } else if (n < 32) {
                g_Ut[(b * RN + (n - 16)) * SN + s] = val;
            } else if (n == 32) {
                g_V[b * SN + s] = val;
            }
        }
    }
}

// =======================================================================
// kernel 2: bias[b,s,t] = sum_r P[b,r,s]*U[b,r,t] + V[b,t]
//   Block 256 = 64 t-lanes (4 t) x 4 s-groups (4 s = 2 s-pairs).
//   P s-paired in regs (no duplication), U duplicated on the fly (ALU pipe),
//   register transpose -> coalesced float4 stores. 2 CTAs/SM + cp.async DB.
// =======================================================================
__global__ __launch_bounds__(256, 2)
void k2_outer(float* __restrict__ out) {
    __shared__ __align__(16) float Us[2][RN * 256];   // 2 x 16 KB
    __shared__ __align__(16) float Vs[2][256];        // 2 x 1 KB

    const int tid = threadIdx.x;
    const int x = tid & 63;          // t quad lane
    const int y = tid >> 6;          // s group 0..3
    const int b = blockIdx.z;
    const int sB = blockIdx.y * 16 + y * 4;     // this thread's 4 s-rows
    const int tQ = blockIdx.x * 1024;

    // P: 2 s-pairs x 16 r, naturally paired across s (64 regs)
    float2 pp[2][RN];
    #pragma unroll
    for (int r = 0; r < RN; r++) {
        const float* src = &g_Pf[(b * RN + r) * SN + sB];
        pp[0][r] = *reinterpret_cast<const float2*>(src);
        pp[1][r] = *reinterpret_cast<const float2*>(src + 2);
    }

    auto stage = [&](int it, int buf) {
        #pragma unroll
        for (int i = 0; i < 4; i++) {
            int idx = tid + 256 * i;
            int r = idx >> 6, t4 = idx & 63;
            cp16(&Us[buf][r * 256 + t4 * 4],
                 &g_Ut[(b * RN + r) * SN + tQ + it * 256 + t4 * 4]);
        }
        if (tid < 64)
            cp16(&Vs[buf][tid * 4], &g_V[b * SN + tQ + it * 256 + tid * 4]);
        cp_commit();
    };

    stage(0, 0);

    for (int it = 0; it < 4; it++) {
        cp_wait0();
        __syncthreads();
        if (it + 1 < 4) stage(it + 1, (it + 1) & 1);
        const int buf = it & 1;
        const int tBase = tQ + it * 256;

        float4 v4 = *reinterpret_cast<const float4*>(&Vs[buf][4 * x]);
        float2 acc[2][4];
        #pragma unroll
        for (int sp = 0; sp < 2; sp++) {
            acc[sp][0] = make_float2(v4.x, v4.x);
            acc[sp][1] = make_float2(v4.y, v4.y);
            acc[sp][2] = make_float2(v4.z, v4.z);
            acc[sp][3] = make_float2(v4.w, v4.w);
        }

        #pragma unroll
        for (int r = 0; r < RN; r++) {
            float4 u4 = *reinterpret_cast<const float4*>(&Us[buf][r * 256 + 4 * x]);
            float2 d0 = make_float2(u4.x, u4.x);
            float2 d1 = make_float2(u4.y, u4.y);
            float2 d2 = make_float2(u4.z, u4.z);
            float2 d3 = make_float2(u4.w, u4.w);
            #pragma unroll
            for (int sp = 0; sp < 2; sp++) {
                acc[sp][0] = ffma2(pp[sp][r], d0, acc[sp][0]);
                acc[sp][1] = ffma2(pp[sp][r], d1, acc[sp][1]);
                acc[sp][2] = ffma2(pp[sp][r], d2, acc[sp][2]);
                acc[sp][3] = ffma2(pp[sp][r], d3, acc[sp][3]);
            }
        }

        // register transpose: s-pairs -> per-s float4 rows, coalesced stores
        #pragma unroll
        for (int sp = 0; sp < 2; sp++) {
            float* o0 = &out[(size_t)(b * SN + sB + 2 * sp) * SN + tBase];
            float* o1 = &out[(size_t)(b * SN + sB + 2 * sp + 1) * SN + tBase];
            *reinterpret_cast<float4*>(&o0[4 * x]) =
                make_float4(acc[sp][0].x, acc[sp][1].x, acc[sp][2].x, acc[sp][3].x);
            *reinterpret_cast<float4*>(&o1[4 * x]) =
                make_float4(acc[sp][0].y, acc[sp][1].y, acc[sp][2].y, acc[sp][3].y);
        }
        __syncthreads();
    }
}

// ---------------- launch ----------------
extern "C" void kernel_launch(void* const* d_in, const int* in_sizes, int n_in,
                              void* d_out, int out_size) {
    const float* hs       = (const float*)d_in[0];
    const float* wc       = (const float*)d_in[1];
    const float* bc       = (const float*)d_in[2];
    const float* we       = (const float*)d_in[3];
    const float* be       = (const float*)d_in[4];
    const float* strength = (const float*)d_in[5];
    float* out = (float*)d_out;

    k1_proj<<<(BN * SN) / K1_BM, 256>>>(hs, wc, bc, we, be, strength);
    k2_outer<<<dim3(4, SN / 16, BN), 256>>>(out);
}